// round 2
// baseline (speedup 1.0000x reference)
#include <cuda_runtime.h>
#include <cuda_bf16.h>
#include <math.h>

// Problem constants (fixed by setup_inputs)
#define BATCH   16
#define LEN     262144
#define NFFT    1024
#define HOP     256
#define NT      1025          // frames
#define NF      513           // rfft bins (valid)
#define NFQ     528           // padded pitch (16 * 33, 16B-aligned rows)
#define NFP     33            // freq patches
#define NTP     65            // time patches
#define NP      2145          // patches per batch
#define KSEL    643           // int(2145*0.3)
#define MAGP    (BATCH*NT*NFQ)

// Scratch (static device memory; no allocation allowed)
__device__ float g_mag[3ll * MAGP];       // [sig][b][t][f(pitch 528)]
__device__ float g_kgs[BATCH * NP];
__device__ float g_pl [BATCH * NP];
__device__ float g_bsel[BATCH];
__device__ float g_bkgs[BATCH];
__device__ int   g_bpos[BATCH];

__device__ __constant__ int BR5[32] = {
    0,16,8,24,4,20,12,28,2,18,10,26,6,22,14,30,
    1,17,9,25,5,21,13,29,3,19,11,27,7,23,15,31 };

// ---------------------------------------------------------------------------
// Fully-unrolled register FFT-32, DIT, expects input already in bit-reversed
// slots (the permutation is folded into the load addressing, which is
// compile-time). Natural-order output. Twiddles are immediates.
// ---------------------------------------------------------------------------
__device__ __forceinline__ void fft32_nr(float* xr, float* xi) {
    constexpr float C32[16] = {
        1.0f,          0.980785280f,  0.923879533f,  0.831469612f,
        0.707106781f,  0.555570233f,  0.382683432f,  0.195090322f,
        0.0f,         -0.195090322f, -0.382683432f, -0.555570233f,
       -0.707106781f, -0.831469612f, -0.923879533f, -0.980785280f };
    constexpr float S32[16] = {
        0.0f,          0.195090322f,  0.382683432f,  0.555570233f,
        0.707106781f,  0.831469612f,  0.923879533f,  0.980785280f,
        1.0f,          0.980785280f,  0.923879533f,  0.831469612f,
        0.707106781f,  0.555570233f,  0.382683432f,  0.195090322f };
#pragma unroll
    for (int s = 1; s <= 5; s++) {
        const int h = 1 << (s - 1);
#pragma unroll
        for (int g = 0; g < 32; g += (1 << s)) {
#pragma unroll
            for (int j = 0; j < h; j++) {
                const float wr =  C32[j << (5 - s)];
                const float wi = -S32[j << (5 - s)];
                const int a = g + j, c = g + j + h;
                float tr = wr * xr[c] - wi * xi[c];
                float ti = wr * xi[c] + wi * xr[c];
                xr[c] = xr[a] - tr; xi[c] = xi[a] - ti;
                xr[a] = xr[a] + tr; xi[a] = xi[a] + ti;
            }
        }
    }
}

// ---------------------------------------------------------------------------
// Kernel 1: STFT magnitudes. One warp = one complex-1024 FFT carrying TWO
// frames (two-for-one real trick). Four-step 32x32:
//   - pass A loads DIRECTLY from global (transposed access is coalesced)
//   - single shared transpose (pitch 33, conflict-free)
//   - pass B output unpacked via conjugate-pair __shfl, coalesced STG
// ---------------------------------------------------------------------------
__global__ __launch_bounds__(128) void stft_kernel(
    const float* __restrict__ xs, const float* __restrict__ xt,
    const float* __restrict__ xg)
{
    const int lane = threadIdx.x & 31;
    const int w    = threadIdx.x >> 5;
    const int pair = blockIdx.x * 4 + w;          // 24624 pairs total (exact)

    int sig = pair / (BATCH * 513);
    int rem = pair - sig * (BATCH * 513);
    int b   = rem / 513;
    int m   = rem - b * 513;

    const float* x = (sig == 0) ? xs : (sig == 1 ? xt : xg);
    x += (size_t)b * LEN;

    __shared__ float SRE[4][1056];
    __shared__ float SIM[4][1056];
    float* sre = SRE[w];
    float* sim = SIM[w];

    const int ta    = 2 * m;
    const bool hasb = (m < 512);                  // frame 2m+1 valid?
    const int base  = ta * HOP - 512;             // reflect-pad origin

    float xr[32], xi[32];

    // ---- Pass A: direct global load (coalesced), FFT over n2 ----
    const int n1 = lane;
#pragma unroll
    for (int n2 = 0; n2 < 32; n2++) {
        int sa = base + n2 * 32 + n1;
        int ia = sa < 0 ? -sa : (sa >= LEN ? 2 * LEN - 2 - sa : sa);
        float va = x[ia];
        float vb = 0.f;
        if (hasb) {
            int sb = sa + HOP;
            int ib = sb < 0 ? -sb : (sb >= LEN ? 2 * LEN - 2 - sb : sb);
            vb = x[ib];
        }
        xr[BR5[n2]] = va;       // BR5[n2] is compile-time after unroll
        xi[BR5[n2]] = vb;
    }
    fft32_nr(xr, xi);

    // ---- twiddle by e^{-2pi i n1 k2 / 1024}, 4 independent chains ----
    {
        float ssn, cc;
        sincospif(-(float)n1 * (1.0f / 512.0f), &ssn, &cc);
        float w1r = cc,                  w1i = ssn;
        float w2r = w1r*w1r - w1i*w1i,   w2i = 2.f*w1r*w1i;
        float w3r = w2r*w1r - w2i*w1i,   w3i = w2r*w1i + w2i*w1r;
        float w4r = w2r*w2r - w2i*w2i,   w4i = 2.f*w2r*w2i;
        float cwr[4] = {1.f, w1r, w2r, w3r};
        float cwi[4] = {0.f, w1i, w2i, w3i};
#pragma unroll
        for (int r = 0; r < 4; r++) {
            float wr = cwr[r], wi = cwi[r];
#pragma unroll
            for (int s5 = 0; s5 < 8; s5++) {
                const int k2 = r + 4 * s5;
                float ar = xr[k2], ai = xi[k2];
                sre[n1 * 33 + k2] = ar * wr - ai * wi;
                sim[n1 * 33 + k2] = ar * wi + ai * wr;
                float nwr = wr * w4r - wi * w4i;
                float nwi = wr * w4i + wi * w4r;
                wr = nwr; wi = nwi;
            }
        }
    }
    __syncwarp();

    // ---- Pass B: transpose read from shared (coalesced), FFT over n1 ----
    const int k2 = lane;
#pragma unroll
    for (int nn = 0; nn < 32; nn++) {
        xr[BR5[nn]] = sre[nn * 33 + k2];
        xi[BR5[nn]] = sim[nn * 33 + k2];
    }
    fft32_nr(xr, xi);
    // thread k2 now holds Z[k2 + 32*k1] in slot k1 (natural order)

    // ---- unpack two real spectra via conjugate-pair shfl; coalesced STG ----
    const int pl = (32 - lane) & 31;   // partner lane
    float* outA = g_mag + (size_t)sig * MAGP + ((size_t)b * NT + ta) * NFQ;
    float* outB = outA + NFQ;

#pragma unroll
    for (int k1 = 0; k1 <= 16; k1++) {
        const int s1 = (31 - k1) & 31;        // partner slot (lanes 1..31)
        const int s0 = (32 - k1) & 31;        // lane-0 self slot
        float yr = __shfl_sync(0xffffffffu, xr[s1], pl);
        float yi = __shfl_sync(0xffffffffu, xi[s1], pl);
        if (lane == 0) { yr = xr[s0]; yi = xi[s0]; }
        const int sz = k1 & 31;
        float zr = xr[sz], zi = xi[sz];

        float ar = 0.5f * (zr + yr), ai = 0.5f * (zi - yi);
        float r2a = ar * ar + ai * ai;
        float ma = r2a * rsqrtf(fmaxf(r2a, 1e-24f));
        ma = fmaxf(ma, 1e-8f);
        float br_ = 0.5f * (zi + yi), bi_ = 0.5f * (yr - zr);
        float r2b = br_ * br_ + bi_ * bi_;
        float mb = r2b * rsqrtf(fmaxf(r2b, 1e-24f));
        mb = fmaxf(mb, 1e-8f);

        if (k1 < 16) {
            int k = 32 * k1 + lane;           // coalesced
            outA[k] = ma;
            if (hasb) outB[k] = mb;
        } else {
            if (lane == 0) {
                outA[512] = ma;
                if (hasb) outB[512] = mb;
            } else if (lane <= 15) {          // f-padding 513..527 = 0
                outA[512 + lane] = 0.f;
                if (hasb) outB[512 + lane] = 0.f;
            }
        }
    }
}

// ---------------------------------------------------------------------------
// Kernel 2: per-patch stats. One warp per patch; pure float4 loads on the
// 528-pitch padded layout (rows 16B-aligned). Only t-edge needs a predicate.
// ---------------------------------------------------------------------------
__global__ __launch_bounds__(256) void patch_kernel() {
    const int lane = threadIdx.x & 31;
    const int wid  = threadIdx.x >> 5;
    const int gp   = blockIdx.x * 8 + wid;         // 34320 total (exact)
    const int b  = gp / NP;
    const int p  = gp - b * NP;
    const int fp = p / NTP;
    const int tp = p - fp * NTP;

    const int dt0 = lane >> 2;       // 0..7
    const int q   = lane & 3;        // quad within 16-float row

    float sas = 0.f, sat = 0.f, ssq = 0.f;
#pragma unroll
    for (int j2 = 0; j2 < 2; j2++) {
        int t = tp * 16 + dt0 + j2 * 8;
        if (t < NT) {
            size_t idx = ((size_t)b * NT + t) * NFQ + fp * 16 + q * 4;
            float4 s4 = *(const float4*)(g_mag + idx);
            float4 t4 = *(const float4*)(g_mag + (size_t)MAGP + idx);
            float4 g4 = *(const float4*)(g_mag + 2ll * MAGP + idx);
            sas += fabsf(s4.x - g4.x) + fabsf(s4.y - g4.y)
                 + fabsf(s4.z - g4.z) + fabsf(s4.w - g4.w);
            sat += fabsf(t4.x - g4.x) + fabsf(t4.y - g4.y)
                 + fabsf(t4.z - g4.z) + fabsf(t4.w - g4.w);
            float dx = s4.x - t4.x, dy = s4.y - t4.y;
            float dz = s4.z - t4.z, dw = s4.w - t4.w;
            ssq += dx * dx + dy * dy + dz * dz + dw * dw;
        }
    }
#pragma unroll
    for (int o = 16; o; o >>= 1) {
        sas += __shfl_down_sync(0xffffffffu, sas, o);
        sat += __shfl_down_sync(0xffffffffu, sat, o);
        ssq += __shfl_down_sync(0xffffffffu, ssq, o);
    }
    if (lane == 0) {
        g_kgs[gp] = (sas - sat) * (1.0f / 256.0f);
        g_pl [gp] = ssq * (1.0f / 256.0f);
    }
}

// ---------------------------------------------------------------------------
// Kernel 3: per-batch top-k selection (exact, index-order tie-break) + stats
// ---------------------------------------------------------------------------
__device__ __forceinline__ int bredI(int v, int* scr) {
    const int tid = threadIdx.x;
#pragma unroll
    for (int o = 16; o; o >>= 1) v += __shfl_down_sync(0xffffffffu, v, o);
    __syncthreads();
    if ((tid & 31) == 0) scr[tid >> 5] = v;
    __syncthreads();
    int r = 0;
#pragma unroll
    for (int j = 0; j < 8; j++) r += scr[j];
    return r;
}
__device__ __forceinline__ float bredF(float v, float* scr) {
    const int tid = threadIdx.x;
#pragma unroll
    for (int o = 16; o; o >>= 1) v += __shfl_down_sync(0xffffffffu, v, o);
    __syncthreads();
    if ((tid & 31) == 0) scr[tid >> 5] = v;
    __syncthreads();
    float r = 0.f;
#pragma unroll
    for (int j = 0; j < 8; j++) r += scr[j];
    return r;
}

__global__ __launch_bounds__(256) void select_kernel() {
    const int b = blockIdx.x, tid = threadIdx.x;
    __shared__ unsigned su[NP];
    __shared__ float    spl[NP];
    __shared__ int      eqidx[NP];
    __shared__ int      iscr[8];
    __shared__ float    fscr[8];
    __shared__ int      eqc;

    float ksum = 0.f; int pcnt = 0;
    for (int i = tid; i < NP; i += 256) {
        float kv = g_kgs[b * NP + i];
        spl[i] = g_pl[b * NP + i];
        unsigned bits = __float_as_uint(kv);
        su[i] = (bits & 0x80000000u) ? ~bits : (bits | 0x80000000u); // order-preserving
        ksum += kv;
        pcnt += (kv > 0.f) ? 1 : 0;
    }
    if (tid == 0) eqc = 0;
    __syncthreads();

    ksum = bredF(ksum, fscr);
    pcnt = bredI(pcnt, iscr);

    // binary search for k-th largest key: max v with count(u >= v) >= KSEL
    unsigned long long lo = 0ull, hi = 0xFFFFFFFFull;
    while (lo < hi) {
        unsigned long long mid = lo + ((hi - lo + 1ull) >> 1);
        int c = 0;
        for (int i = tid; i < NP; i += 256)
            c += ((unsigned long long)su[i] >= mid) ? 1 : 0;
        c = bredI(c, iscr);
        if (c >= KSEL) lo = mid; else hi = mid - 1ull;
    }
    const unsigned v = (unsigned)lo;

    int cgt = 0; float ssel = 0.f;
    for (int i = tid; i < NP; i += 256) {
        unsigned u = su[i];
        if (u > v) { cgt++; ssel += spl[i]; }
        else if (u == v) { int pos = atomicAdd(&eqc, 1); eqidx[pos] = i; }
    }
    cgt  = bredI(cgt, iscr);
    ssel = bredF(ssel, fscr);
    __syncthreads();

    if (tid == 0) {
        int need = KSEL - cgt;         // >= 1 by construction
        int ce   = eqc;
        float extra = 0.f;
        if (need >= ce) {
            for (int j = 0; j < ce; j++) extra += spl[eqidx[j]];
        } else {
            // take 'need' equal-valued patches with SMALLEST indices (top_k tie rule)
            int last = -1;
            for (int t2 = 0; t2 < need; t2++) {
                int mn = 0x7fffffff;
                for (int j = 0; j < ce; j++) {
                    int ix = eqidx[j];
                    if (ix > last && ix < mn) mn = ix;
                }
                extra += spl[mn];
                last = mn;
            }
        }
        g_bsel[b] = (ssel + extra) * (1.0f / (float)KSEL);
        g_bkgs[b] = ksum;
        g_bpos[b] = pcnt;
    }
}

// ---------------------------------------------------------------------------
// Kernel 4: finalize the 4 scalars
// ---------------------------------------------------------------------------
__global__ void final_kernel(float* __restrict__ out) {
    const int t = threadIdx.x;
    float s  = (t < BATCH) ? g_bsel[t] : 0.f;
    float kg = (t < BATCH) ? g_bkgs[t] : 0.f;
    float pc = (t < BATCH) ? (float)g_bpos[t] : 0.f;
#pragma unroll
    for (int o = 16; o; o >>= 1) {
        s  += __shfl_down_sync(0xffffffffu, s,  o);
        kg += __shfl_down_sync(0xffffffffu, kg, o);
        pc += __shfl_down_sync(0xffffffffu, pc, o);
    }
    if (t == 0) {
        out[0] = s * (1.0f / (float)BATCH);                      // loss
        out[1] = (float)KSEL / (float)NP;                        // sel_ratio
        out[2] = kg / (float)(BATCH * NP);                       // kgs_mean
        out[3] = pc / (float)(BATCH * NP);                       // kgs_pos_ratio
    }
}

extern "C" void kernel_launch(void* const* d_in, const int* in_sizes, int n_in,
                              void* d_out, int out_size) {
    const float* xs = (const float*)d_in[0];
    const float* xt = (const float*)d_in[1];
    const float* xg = (const float*)d_in[2];
    float* out = (float*)d_out;

    stft_kernel<<<6156, 128>>>(xs, xt, xg);   // 24624 frame-pairs, 4 per block
    patch_kernel<<<4290, 256>>>();            // 34320 patches, 8 per block
    select_kernel<<<BATCH, 256>>>();
    final_kernel<<<1, 32>>>(out);
}

// round 3
// speedup vs baseline: 1.0858x; 1.0858x over previous
#include <cuda_runtime.h>
#include <cuda_bf16.h>
#include <math.h>

// Problem constants (fixed by setup_inputs)
#define BATCH   16
#define LEN     262144
#define NFFT    1024
#define HOP     256
#define NT      1025          // frames
#define NF      513           // rfft bins (valid)
#define NFQ     528           // padded pitch (16 * 33, 16B-aligned rows)
#define NFP     33            // freq patches
#define NTP     65            // time patches
#define NP      2145          // patches per batch
#define KSEL    643           // int(2145*0.3)
#define MAGP    (BATCH*NT*NFQ)

// Scratch (static device memory; no allocation allowed)
__device__ float g_mag[3ll * MAGP];       // [sig][b][t][f(pitch 528)]
__device__ float g_kgs[BATCH * NP];
__device__ float g_pl [BATCH * NP];
__device__ float g_bsel[BATCH];
__device__ float g_bkgs[BATCH];
__device__ int   g_bpos[BATCH];

// Compile-time 5-bit bit-reverse (folds to immediates under #pragma unroll).
// NEVER a memory table: runtime-valued indices would demote xr/xi to local.
__device__ __host__ __forceinline__ constexpr int brev5(int j) {
    return ((j & 1) << 4) | ((j & 2) << 2) | (j & 4) | ((j & 8) >> 2) | ((j & 16) >> 4);
}

// ---------------------------------------------------------------------------
// Fully-unrolled register FFT-32, DIT, input already in bit-reversed slots,
// natural-order output. All indices and twiddles are compile-time constants.
// ---------------------------------------------------------------------------
__device__ __forceinline__ void fft32_nr(float* xr, float* xi) {
    constexpr float C32[16] = {
        1.0f,          0.980785280f,  0.923879533f,  0.831469612f,
        0.707106781f,  0.555570233f,  0.382683432f,  0.195090322f,
        0.0f,         -0.195090322f, -0.382683432f, -0.555570233f,
       -0.707106781f, -0.831469612f, -0.923879533f, -0.980785280f };
    constexpr float S32[16] = {
        0.0f,          0.195090322f,  0.382683432f,  0.555570233f,
        0.707106781f,  0.831469612f,  0.923879533f,  0.980785280f,
        1.0f,          0.980785280f,  0.923879533f,  0.831469612f,
        0.707106781f,  0.555570233f,  0.382683432f,  0.195090322f };
#pragma unroll
    for (int s = 1; s <= 5; s++) {
        const int h = 1 << (s - 1);
#pragma unroll
        for (int g = 0; g < 32; g += (1 << s)) {
#pragma unroll
            for (int j = 0; j < h; j++) {
                const float wr =  C32[j << (5 - s)];
                const float wi = -S32[j << (5 - s)];
                const int a = g + j, c = g + j + h;
                float tr = wr * xr[c] - wi * xi[c];
                float ti = wr * xi[c] + wi * xr[c];
                xr[c] = xr[a] - tr; xi[c] = xi[a] - ti;
                xr[a] = xr[a] + tr; xi[a] = xi[a] + ti;
            }
        }
    }
}

// ---------------------------------------------------------------------------
// Kernel 1: STFT magnitudes. One warp = one complex-1024 FFT carrying TWO
// frames (two-for-one real trick). Four-step 32x32:
//   - pass A loads DIRECTLY from global (coalesced)
//   - single shared transpose (pitch 33, conflict-free)
//   - pass B output unpacked via conjugate-pair __shfl, coalesced STG
// __launch_bounds__(128,1): allow full register budget -> no spill.
// ---------------------------------------------------------------------------
__global__ __launch_bounds__(128, 1) void stft_kernel(
    const float* __restrict__ xs, const float* __restrict__ xt,
    const float* __restrict__ xg)
{
    const int lane = threadIdx.x & 31;
    const int w    = threadIdx.x >> 5;
    const int pair = blockIdx.x * 4 + w;          // 24624 pairs total (exact)

    int sig = pair / (BATCH * 513);
    int rem = pair - sig * (BATCH * 513);
    int b   = rem / 513;
    int m   = rem - b * 513;

    const float* x = (sig == 0) ? xs : (sig == 1 ? xt : xg);
    x += (size_t)b * LEN;

    __shared__ float SRE[4][1056];
    __shared__ float SIM[4][1056];
    float* sre = SRE[w];
    float* sim = SIM[w];

    const int ta    = 2 * m;
    const bool hasb = (m < 512);                  // frame 2m+1 valid?
    const int base  = ta * HOP - 512;             // reflect-pad origin

    float xr[32], xi[32];

    // ---- Pass A: direct global load (coalesced), FFT over n2 ----
    const int n1 = lane;
#pragma unroll
    for (int n2 = 0; n2 < 32; n2++) {
        int sa = base + n2 * 32 + n1;
        int ia = sa < 0 ? -sa : (sa >= LEN ? 2 * LEN - 2 - sa : sa);
        float va = x[ia];
        float vb = 0.f;
        if (hasb) {
            int sb = sa + HOP;
            int ib = sb < 0 ? -sb : (sb >= LEN ? 2 * LEN - 2 - sb : sb);
            vb = x[ib];
        }
        xr[brev5(n2)] = va;       // brev5(n2) is a literal constant
        xi[brev5(n2)] = vb;
    }
    fft32_nr(xr, xi);

    // ---- twiddle by e^{-2pi i n1 k2 / 1024}, 4 independent chains ----
    {
        float ssn, cc;
        sincospif(-(float)n1 * (1.0f / 512.0f), &ssn, &cc);
        float w1r = cc,                  w1i = ssn;
        float w2r = w1r*w1r - w1i*w1i,   w2i = 2.f*w1r*w1i;
        float w3r = w2r*w1r - w2i*w1i,   w3i = w2r*w1i + w2i*w1r;
        float w4r = w2r*w2r - w2i*w2i,   w4i = 2.f*w2r*w2i;
#pragma unroll
        for (int r = 0; r < 4; r++) {
            float wr = (r == 0) ? 1.f : (r == 1 ? w1r : (r == 2 ? w2r : w3r));
            float wi = (r == 0) ? 0.f : (r == 1 ? w1i : (r == 2 ? w2i : w3i));
#pragma unroll
            for (int s5 = 0; s5 < 8; s5++) {
                const int k2 = r + 4 * s5;
                float ar = xr[k2], ai = xi[k2];
                sre[n1 * 33 + k2] = ar * wr - ai * wi;
                sim[n1 * 33 + k2] = ar * wi + ai * wr;
                float nwr = wr * w4r - wi * w4i;
                float nwi = wr * w4i + wi * w4r;
                wr = nwr; wi = nwi;
            }
        }
    }
    __syncwarp();

    // ---- Pass B: transpose read from shared (coalesced), FFT over n1 ----
    const int k2 = lane;
#pragma unroll
    for (int nn = 0; nn < 32; nn++) {
        xr[brev5(nn)] = sre[nn * 33 + k2];
        xi[brev5(nn)] = sim[nn * 33 + k2];
    }
    fft32_nr(xr, xi);
    // thread k2 now holds Z[k2 + 32*k1] in slot k1 (natural order)

    // ---- unpack two real spectra via conjugate-pair shfl; coalesced STG ----
    const int pl = (32 - lane) & 31;   // partner lane
    float* outA = g_mag + (size_t)sig * MAGP + ((size_t)b * NT + ta) * NFQ;
    float* outB = outA + NFQ;

#pragma unroll
    for (int k1 = 0; k1 <= 16; k1++) {
        const int s1 = (31 - k1) & 31;        // partner slot (lanes 1..31)
        const int s0 = (32 - k1) & 31;        // lane-0 self slot
        float yr = __shfl_sync(0xffffffffu, xr[s1], pl);
        float yi = __shfl_sync(0xffffffffu, xi[s1], pl);
        if (lane == 0) { yr = xr[s0]; yi = xi[s0]; }
        const int sz = k1 & 31;
        float zr = xr[sz], zi = xi[sz];

        float ar = 0.5f * (zr + yr), ai = 0.5f * (zi - yi);
        float r2a = ar * ar + ai * ai;
        float ma = r2a * rsqrtf(fmaxf(r2a, 1e-24f));
        ma = fmaxf(ma, 1e-8f);
        float br_ = 0.5f * (zi + yi), bi_ = 0.5f * (yr - zr);
        float r2b = br_ * br_ + bi_ * bi_;
        float mb = r2b * rsqrtf(fmaxf(r2b, 1e-24f));
        mb = fmaxf(mb, 1e-8f);

        if (k1 < 16) {
            int k = 32 * k1 + lane;           // coalesced
            outA[k] = ma;
            if (hasb) outB[k] = mb;
        } else {
            if (lane == 0) {
                outA[512] = ma;
                if (hasb) outB[512] = mb;
            } else if (lane <= 15) {          // f-padding 513..527 = 0
                outA[512 + lane] = 0.f;
                if (hasb) outB[512 + lane] = 0.f;
            }
        }
    }
}

// ---------------------------------------------------------------------------
// Kernel 2: per-patch stats. One warp per patch; pure float4 loads on the
// 528-pitch padded layout (rows 16B-aligned). Only t-edge needs a predicate.
// ---------------------------------------------------------------------------
__global__ __launch_bounds__(256) void patch_kernel() {
    const int lane = threadIdx.x & 31;
    const int wid  = threadIdx.x >> 5;
    const int gp   = blockIdx.x * 8 + wid;         // 34320 total (exact)
    const int b  = gp / NP;
    const int p  = gp - b * NP;
    const int fp = p / NTP;
    const int tp = p - fp * NTP;

    const int dt0 = lane >> 2;       // 0..7
    const int q   = lane & 3;        // quad within 16-float row

    float sas = 0.f, sat = 0.f, ssq = 0.f;
#pragma unroll
    for (int j2 = 0; j2 < 2; j2++) {
        int t = tp * 16 + dt0 + j2 * 8;
        if (t < NT) {
            size_t idx = ((size_t)b * NT + t) * NFQ + fp * 16 + q * 4;
            float4 s4 = *(const float4*)(g_mag + idx);
            float4 t4 = *(const float4*)(g_mag + (size_t)MAGP + idx);
            float4 g4 = *(const float4*)(g_mag + 2ll * MAGP + idx);
            sas += fabsf(s4.x - g4.x) + fabsf(s4.y - g4.y)
                 + fabsf(s4.z - g4.z) + fabsf(s4.w - g4.w);
            sat += fabsf(t4.x - g4.x) + fabsf(t4.y - g4.y)
                 + fabsf(t4.z - g4.z) + fabsf(t4.w - g4.w);
            float dx = s4.x - t4.x, dy = s4.y - t4.y;
            float dz = s4.z - t4.z, dw = s4.w - t4.w;
            ssq += dx * dx + dy * dy + dz * dz + dw * dw;
        }
    }
#pragma unroll
    for (int o = 16; o; o >>= 1) {
        sas += __shfl_down_sync(0xffffffffu, sas, o);
        sat += __shfl_down_sync(0xffffffffu, sat, o);
        ssq += __shfl_down_sync(0xffffffffu, ssq, o);
    }
    if (lane == 0) {
        g_kgs[gp] = (sas - sat) * (1.0f / 256.0f);
        g_pl [gp] = ssq * (1.0f / 256.0f);
    }
}

// ---------------------------------------------------------------------------
// Kernel 3: per-batch top-k selection (exact, index-order tie-break) + stats
// ---------------------------------------------------------------------------
__device__ __forceinline__ int bredI(int v, int* scr) {
    const int tid = threadIdx.x;
#pragma unroll
    for (int o = 16; o; o >>= 1) v += __shfl_down_sync(0xffffffffu, v, o);
    __syncthreads();
    if ((tid & 31) == 0) scr[tid >> 5] = v;
    __syncthreads();
    int r = 0;
#pragma unroll
    for (int j = 0; j < 8; j++) r += scr[j];
    return r;
}
__device__ __forceinline__ float bredF(float v, float* scr) {
    const int tid = threadIdx.x;
#pragma unroll
    for (int o = 16; o; o >>= 1) v += __shfl_down_sync(0xffffffffu, v, o);
    __syncthreads();
    if ((tid & 31) == 0) scr[tid >> 5] = v;
    __syncthreads();
    float r = 0.f;
#pragma unroll
    for (int j = 0; j < 8; j++) r += scr[j];
    return r;
}

__global__ __launch_bounds__(256) void select_kernel() {
    const int b = blockIdx.x, tid = threadIdx.x;
    __shared__ unsigned su[NP];
    __shared__ float    spl[NP];
    __shared__ int      eqidx[NP];
    __shared__ int      iscr[8];
    __shared__ float    fscr[8];
    __shared__ int      eqc;

    float ksum = 0.f; int pcnt = 0;
    for (int i = tid; i < NP; i += 256) {
        float kv = g_kgs[b * NP + i];
        spl[i] = g_pl[b * NP + i];
        unsigned bits = __float_as_uint(kv);
        su[i] = (bits & 0x80000000u) ? ~bits : (bits | 0x80000000u); // order-preserving
        ksum += kv;
        pcnt += (kv > 0.f) ? 1 : 0;
    }
    if (tid == 0) eqc = 0;
    __syncthreads();

    ksum = bredF(ksum, fscr);
    pcnt = bredI(pcnt, iscr);

    // binary search for k-th largest key: max v with count(u >= v) >= KSEL
    unsigned long long lo = 0ull, hi = 0xFFFFFFFFull;
    while (lo < hi) {
        unsigned long long mid = lo + ((hi - lo + 1ull) >> 1);
        int c = 0;
        for (int i = tid; i < NP; i += 256)
            c += ((unsigned long long)su[i] >= mid) ? 1 : 0;
        c = bredI(c, iscr);
        if (c >= KSEL) lo = mid; else hi = mid - 1ull;
    }
    const unsigned v = (unsigned)lo;

    int cgt = 0; float ssel = 0.f;
    for (int i = tid; i < NP; i += 256) {
        unsigned u = su[i];
        if (u > v) { cgt++; ssel += spl[i]; }
        else if (u == v) { int pos = atomicAdd(&eqc, 1); eqidx[pos] = i; }
    }
    cgt  = bredI(cgt, iscr);
    ssel = bredF(ssel, fscr);
    __syncthreads();

    if (tid == 0) {
        int need = KSEL - cgt;         // >= 1 by construction
        int ce   = eqc;
        float extra = 0.f;
        if (need >= ce) {
            for (int j = 0; j < ce; j++) extra += spl[eqidx[j]];
        } else {
            // take 'need' equal-valued patches with SMALLEST indices (top_k tie rule)
            int last = -1;
            for (int t2 = 0; t2 < need; t2++) {
                int mn = 0x7fffffff;
                for (int j = 0; j < ce; j++) {
                    int ix = eqidx[j];
                    if (ix > last && ix < mn) mn = ix;
                }
                extra += spl[mn];
                last = mn;
            }
        }
        g_bsel[b] = (ssel + extra) * (1.0f / (float)KSEL);
        g_bkgs[b] = ksum;
        g_bpos[b] = pcnt;
    }
}

// ---------------------------------------------------------------------------
// Kernel 4: finalize the 4 scalars
// ---------------------------------------------------------------------------
__global__ void final_kernel(float* __restrict__ out) {
    const int t = threadIdx.x;
    float s  = (t < BATCH) ? g_bsel[t] : 0.f;
    float kg = (t < BATCH) ? g_bkgs[t] : 0.f;
    float pc = (t < BATCH) ? (float)g_bpos[t] : 0.f;
#pragma unroll
    for (int o = 16; o; o >>= 1) {
        s  += __shfl_down_sync(0xffffffffu, s,  o);
        kg += __shfl_down_sync(0xffffffffu, kg, o);
        pc += __shfl_down_sync(0xffffffffu, pc, o);
    }
    if (t == 0) {
        out[0] = s * (1.0f / (float)BATCH);                      // loss
        out[1] = (float)KSEL / (float)NP;                        // sel_ratio
        out[2] = kg / (float)(BATCH * NP);                       // kgs_mean
        out[3] = pc / (float)(BATCH * NP);                       // kgs_pos_ratio
    }
}

extern "C" void kernel_launch(void* const* d_in, const int* in_sizes, int n_in,
                              void* d_out, int out_size) {
    const float* xs = (const float*)d_in[0];
    const float* xt = (const float*)d_in[1];
    const float* xg = (const float*)d_in[2];
    float* out = (float*)d_out;

    stft_kernel<<<6156, 128>>>(xs, xt, xg);   // 24624 frame-pairs, 4 per block
    patch_kernel<<<4290, 256>>>();            // 34320 patches, 8 per block
    select_kernel<<<BATCH, 256>>>();
    final_kernel<<<1, 32>>>(out);
}

// round 4
// speedup vs baseline: 1.1046x; 1.0173x over previous
#include <cuda_runtime.h>
#include <cuda_bf16.h>
#include <math.h>

// Problem constants (fixed by setup_inputs)
#define BATCH   16
#define LEN     262144
#define NFFT    1024
#define HOP     256
#define NT      1025          // frames
#define NF      513           // rfft bins (valid)
#define NFQ     528           // padded pitch (16 * 33, 16B-aligned rows)
#define NFP     33            // freq patches
#define NTP     65            // time patches
#define NP      2145          // patches per batch
#define KSEL    643           // int(2145*0.3)
#define MAGP    (BATCH*NT*NFQ)

// Scratch (static device memory; no allocation allowed)
__device__ float g_mag[3ll * MAGP];       // [sig][b][t][f(pitch 528)]
__device__ float g_kgs[BATCH * NP];
__device__ float g_pl [BATCH * NP];
__device__ float g_bsel[BATCH];
__device__ float g_bkgs[BATCH];
__device__ int   g_bpos[BATCH];

// Compile-time 5-bit bit-reverse (folds to immediates under #pragma unroll).
__device__ __host__ __forceinline__ constexpr int brev5(int j) {
    return ((j & 1) << 4) | ((j & 2) << 2) | (j & 4) | ((j & 8) >> 2) | ((j & 16) >> 4);
}

// ---------------------------------------------------------------------------
// Fully-unrolled register FFT-32, DIT, input already in bit-reversed slots,
// natural-order output. All indices and twiddles are compile-time constants.
// ---------------------------------------------------------------------------
__device__ __forceinline__ void fft32_nr(float* xr, float* xi) {
    constexpr float C32[16] = {
        1.0f,          0.980785280f,  0.923879533f,  0.831469612f,
        0.707106781f,  0.555570233f,  0.382683432f,  0.195090322f,
        0.0f,         -0.195090322f, -0.382683432f, -0.555570233f,
       -0.707106781f, -0.831469612f, -0.923879533f, -0.980785280f };
    constexpr float S32[16] = {
        0.0f,          0.195090322f,  0.382683432f,  0.555570233f,
        0.707106781f,  0.831469612f,  0.923879533f,  0.980785280f,
        1.0f,          0.980785280f,  0.923879533f,  0.831469612f,
        0.707106781f,  0.555570233f,  0.382683432f,  0.195090322f };
#pragma unroll
    for (int s = 1; s <= 5; s++) {
        const int h = 1 << (s - 1);
#pragma unroll
        for (int g = 0; g < 32; g += (1 << s)) {
#pragma unroll
            for (int j = 0; j < h; j++) {
                const float wr =  C32[j << (5 - s)];
                const float wi = -S32[j << (5 - s)];
                const int a = g + j, c = g + j + h;
                float tr = wr * xr[c] - wi * xi[c];
                float ti = wr * xi[c] + wi * xr[c];
                xr[c] = xr[a] - tr; xi[c] = xi[a] - ti;
                xr[a] = xr[a] + tr; xi[a] = xi[a] + ti;
            }
        }
    }
}

// ---------------------------------------------------------------------------
// Kernel 1: STFT magnitudes. One warp = one complex-1024 FFT carrying TWO
// frames (two-for-one real trick). Four-step 32x32.
// __launch_bounds__(128,4): cap regs at 128 -> 4 blocks/SM -> 4 warps/SMSP.
// This is the occupancy experiment: prior rounds were issue-starved at
// 2 warps/SMSP from unbounded register allocation.
// ---------------------------------------------------------------------------
__global__ __launch_bounds__(128, 4) void stft_kernel(
    const float* __restrict__ xs, const float* __restrict__ xt,
    const float* __restrict__ xg)
{
    const int lane = threadIdx.x & 31;
    const int w    = threadIdx.x >> 5;
    const int pair = blockIdx.x * 4 + w;          // 24624 pairs total (exact)

    int sig = pair / (BATCH * 513);
    int rem = pair - sig * (BATCH * 513);
    int b   = rem / 513;
    int m   = rem - b * 513;

    const float* x = (sig == 0) ? xs : (sig == 1 ? xt : xg);
    x += (size_t)b * LEN;

    __shared__ float SRE[4][1056];
    __shared__ float SIM[4][1056];
    float* sre = SRE[w];
    float* sim = SIM[w];

    const int ta    = 2 * m;
    const bool hasb = (m < 512);                  // frame 2m+1 valid?
    const int base  = ta * HOP - 512;             // reflect-pad origin

    float xr[32], xi[32];

    // ---- Pass A: direct global load (coalesced), FFT over n2 ----
    // Branchless reflect: for s in [-512, LEN+512), index = min(|s|, |2L-2-s|).
    const int n1 = lane;
#pragma unroll
    for (int n2 = 0; n2 < 32; n2++) {
        int sa = base + n2 * 32 + n1;
        int ia = min(abs(sa), abs(2 * LEN - 2 - sa));
        int sb = sa + HOP;
        int ib = min(abs(sb), abs(2 * LEN - 2 - sb));
        float va = x[ia];
        float vb = hasb ? x[ib] : 0.f;
        xr[brev5(n2)] = va;       // brev5(n2) is a literal constant
        xi[brev5(n2)] = vb;
    }
    fft32_nr(xr, xi);

    // ---- twiddle by e^{-2pi i n1 k2 / 1024}, 4 independent chains ----
    {
        float ssn, cc;
        sincospif(-(float)n1 * (1.0f / 512.0f), &ssn, &cc);
        float w1r = cc,                  w1i = ssn;
        float w2r = w1r*w1r - w1i*w1i,   w2i = 2.f*w1r*w1i;
        float w3r = w2r*w1r - w2i*w1i,   w3i = w2r*w1i + w2i*w1r;
        float w4r = w2r*w2r - w2i*w2i,   w4i = 2.f*w2r*w2i;
#pragma unroll
        for (int r = 0; r < 4; r++) {
            float wr = (r == 0) ? 1.f : (r == 1 ? w1r : (r == 2 ? w2r : w3r));
            float wi = (r == 0) ? 0.f : (r == 1 ? w1i : (r == 2 ? w2i : w3i));
#pragma unroll
            for (int s5 = 0; s5 < 8; s5++) {
                const int k2 = r + 4 * s5;
                float ar = xr[k2], ai = xi[k2];
                sre[n1 * 33 + k2] = ar * wr - ai * wi;
                sim[n1 * 33 + k2] = ar * wi + ai * wr;
                float nwr = wr * w4r - wi * w4i;
                float nwi = wr * w4i + wi * w4r;
                wr = nwr; wi = nwi;
            }
        }
    }
    __syncwarp();

    // ---- Pass B: transpose read from shared (coalesced), FFT over n1 ----
    const int k2 = lane;
#pragma unroll
    for (int nn = 0; nn < 32; nn++) {
        xr[brev5(nn)] = sre[nn * 33 + k2];
        xi[brev5(nn)] = sim[nn * 33 + k2];
    }
    fft32_nr(xr, xi);
    // thread k2 now holds Z[k2 + 32*k1] in slot k1 (natural order)

    // ---- unpack two real spectra via conjugate-pair shfl; coalesced STG ----
    const int pl = (32 - lane) & 31;   // partner lane
    float* outA = g_mag + (size_t)sig * MAGP + ((size_t)b * NT + ta) * NFQ;
    float* outB = outA + NFQ;

#pragma unroll
    for (int k1 = 0; k1 <= 16; k1++) {
        const int s1 = (31 - k1) & 31;        // partner slot (lanes 1..31)
        const int s0 = (32 - k1) & 31;        // lane-0 self slot
        float yr = __shfl_sync(0xffffffffu, xr[s1], pl);
        float yi = __shfl_sync(0xffffffffu, xi[s1], pl);
        if (lane == 0) { yr = xr[s0]; yi = xi[s0]; }
        const int sz = k1 & 31;
        float zr = xr[sz], zi = xi[sz];

        float ar = 0.5f * (zr + yr), ai = 0.5f * (zi - yi);
        float r2a = ar * ar + ai * ai;
        float ma = r2a * rsqrtf(fmaxf(r2a, 1e-24f));
        ma = fmaxf(ma, 1e-8f);
        float br_ = 0.5f * (zi + yi), bi_ = 0.5f * (yr - zr);
        float r2b = br_ * br_ + bi_ * bi_;
        float mb = r2b * rsqrtf(fmaxf(r2b, 1e-24f));
        mb = fmaxf(mb, 1e-8f);

        if (k1 < 16) {
            int k = 32 * k1 + lane;           // coalesced
            outA[k] = ma;
            if (hasb) outB[k] = mb;
        } else {
            if (lane == 0) {
                outA[512] = ma;
                if (hasb) outB[512] = mb;
            } else if (lane <= 15) {          // f-padding 513..527 = 0
                outA[512 + lane] = 0.f;
                if (hasb) outB[512 + lane] = 0.f;
            }
        }
    }
}

// ---------------------------------------------------------------------------
// Kernel 2: per-patch stats. One warp per patch; pure float4 loads on the
// 528-pitch padded layout (rows 16B-aligned). Only t-edge needs a predicate.
// ---------------------------------------------------------------------------
__global__ __launch_bounds__(256) void patch_kernel() {
    const int lane = threadIdx.x & 31;
    const int wid  = threadIdx.x >> 5;
    const int gp   = blockIdx.x * 8 + wid;         // 34320 total (exact)
    const int b  = gp / NP;
    const int p  = gp - b * NP;
    const int fp = p / NTP;
    const int tp = p - fp * NTP;

    const int dt0 = lane >> 2;       // 0..7
    const int q   = lane & 3;        // quad within 16-float row

    float sas = 0.f, sat = 0.f, ssq = 0.f;
#pragma unroll
    for (int j2 = 0; j2 < 2; j2++) {
        int t = tp * 16 + dt0 + j2 * 8;
        if (t < NT) {
            size_t idx = ((size_t)b * NT + t) * NFQ + fp * 16 + q * 4;
            float4 s4 = *(const float4*)(g_mag + idx);
            float4 t4 = *(const float4*)(g_mag + (size_t)MAGP + idx);
            float4 g4 = *(const float4*)(g_mag + 2ll * MAGP + idx);
            sas += fabsf(s4.x - g4.x) + fabsf(s4.y - g4.y)
                 + fabsf(s4.z - g4.z) + fabsf(s4.w - g4.w);
            sat += fabsf(t4.x - g4.x) + fabsf(t4.y - g4.y)
                 + fabsf(t4.z - g4.z) + fabsf(t4.w - g4.w);
            float dx = s4.x - t4.x, dy = s4.y - t4.y;
            float dz = s4.z - t4.z, dw = s4.w - t4.w;
            ssq += dx * dx + dy * dy + dz * dz + dw * dw;
        }
    }
#pragma unroll
    for (int o = 16; o; o >>= 1) {
        sas += __shfl_down_sync(0xffffffffu, sas, o);
        sat += __shfl_down_sync(0xffffffffu, sat, o);
        ssq += __shfl_down_sync(0xffffffffu, ssq, o);
    }
    if (lane == 0) {
        g_kgs[gp] = (sas - sat) * (1.0f / 256.0f);
        g_pl [gp] = ssq * (1.0f / 256.0f);
    }
}

// ---------------------------------------------------------------------------
// Kernel 3: per-batch top-k selection (exact, index-order tie-break) + stats
// ---------------------------------------------------------------------------
__device__ __forceinline__ int bredI(int v, int* scr) {
    const int tid = threadIdx.x;
#pragma unroll
    for (int o = 16; o; o >>= 1) v += __shfl_down_sync(0xffffffffu, v, o);
    __syncthreads();
    if ((tid & 31) == 0) scr[tid >> 5] = v;
    __syncthreads();
    int r = 0;
#pragma unroll
    for (int j = 0; j < 8; j++) r += scr[j];
    return r;
}
__device__ __forceinline__ float bredF(float v, float* scr) {
    const int tid = threadIdx.x;
#pragma unroll
    for (int o = 16; o; o >>= 1) v += __shfl_down_sync(0xffffffffu, v, o);
    __syncthreads();
    if ((tid & 31) == 0) scr[tid >> 5] = v;
    __syncthreads();
    float r = 0.f;
#pragma unroll
    for (int j = 0; j < 8; j++) r += scr[j];
    return r;
}

__global__ __launch_bounds__(256) void select_kernel() {
    const int b = blockIdx.x, tid = threadIdx.x;
    __shared__ unsigned su[NP];
    __shared__ float    spl[NP];
    __shared__ int      eqidx[NP];
    __shared__ int      iscr[8];
    __shared__ float    fscr[8];
    __shared__ int      eqc;

    float ksum = 0.f; int pcnt = 0;
    for (int i = tid; i < NP; i += 256) {
        float kv = g_kgs[b * NP + i];
        spl[i] = g_pl[b * NP + i];
        unsigned bits = __float_as_uint(kv);
        su[i] = (bits & 0x80000000u) ? ~bits : (bits | 0x80000000u); // order-preserving
        ksum += kv;
        pcnt += (kv > 0.f) ? 1 : 0;
    }
    if (tid == 0) eqc = 0;
    __syncthreads();

    ksum = bredF(ksum, fscr);
    pcnt = bredI(pcnt, iscr);

    // binary search for k-th largest key: max v with count(u >= v) >= KSEL
    unsigned long long lo = 0ull, hi = 0xFFFFFFFFull;
    while (lo < hi) {
        unsigned long long mid = lo + ((hi - lo + 1ull) >> 1);
        int c = 0;
        for (int i = tid; i < NP; i += 256)
            c += ((unsigned long long)su[i] >= mid) ? 1 : 0;
        c = bredI(c, iscr);
        if (c >= KSEL) lo = mid; else hi = mid - 1ull;
    }
    const unsigned v = (unsigned)lo;

    int cgt = 0; float ssel = 0.f;
    for (int i = tid; i < NP; i += 256) {
        unsigned u = su[i];
        if (u > v) { cgt++; ssel += spl[i]; }
        else if (u == v) { int pos = atomicAdd(&eqc, 1); eqidx[pos] = i; }
    }
    cgt  = bredI(cgt, iscr);
    ssel = bredF(ssel, fscr);
    __syncthreads();

    if (tid == 0) {
        int need = KSEL - cgt;         // >= 1 by construction
        int ce   = eqc;
        float extra = 0.f;
        if (need >= ce) {
            for (int j = 0; j < ce; j++) extra += spl[eqidx[j]];
        } else {
            // take 'need' equal-valued patches with SMALLEST indices (top_k tie rule)
            int last = -1;
            for (int t2 = 0; t2 < need; t2++) {
                int mn = 0x7fffffff;
                for (int j = 0; j < ce; j++) {
                    int ix = eqidx[j];
                    if (ix > last && ix < mn) mn = ix;
                }
                extra += spl[mn];
                last = mn;
            }
        }
        g_bsel[b] = (ssel + extra) * (1.0f / (float)KSEL);
        g_bkgs[b] = ksum;
        g_bpos[b] = pcnt;
    }
}

// ---------------------------------------------------------------------------
// Kernel 4: finalize the 4 scalars
// ---------------------------------------------------------------------------
__global__ void final_kernel(float* __restrict__ out) {
    const int t = threadIdx.x;
    float s  = (t < BATCH) ? g_bsel[t] : 0.f;
    float kg = (t < BATCH) ? g_bkgs[t] : 0.f;
    float pc = (t < BATCH) ? (float)g_bpos[t] : 0.f;
#pragma unroll
    for (int o = 16; o; o >>= 1) {
        s  += __shfl_down_sync(0xffffffffu, s,  o);
        kg += __shfl_down_sync(0xffffffffu, kg, o);
        pc += __shfl_down_sync(0xffffffffu, pc, o);
    }
    if (t == 0) {
        out[0] = s * (1.0f / (float)BATCH);                      // loss
        out[1] = (float)KSEL / (float)NP;                        // sel_ratio
        out[2] = kg / (float)(BATCH * NP);                       // kgs_mean
        out[3] = pc / (float)(BATCH * NP);                       // kgs_pos_ratio
    }
}

extern "C" void kernel_launch(void* const* d_in, const int* in_sizes, int n_in,
                              void* d_out, int out_size) {
    const float* xs = (const float*)d_in[0];
    const float* xt = (const float*)d_in[1];
    const float* xg = (const float*)d_in[2];
    float* out = (float*)d_out;

    stft_kernel<<<6156, 128>>>(xs, xt, xg);   // 24624 frame-pairs, 4 per block
    patch_kernel<<<4290, 256>>>();            // 34320 patches, 8 per block
    select_kernel<<<BATCH, 256>>>();
    final_kernel<<<1, 32>>>(out);
}